// round 17
// baseline (speedup 1.0000x reference)
#include <cuda_runtime.h>

// ---------------- problem constants ----------------
#define T_    512
#define B_    64
#define DIN_  256
#define H_    1024
#define G4_   4096
#define DOUT_ 256

// ---------------- tiling ----------------
#define NCTA  128          // CTAs; each owns NU hidden units
#define NU    8            // hidden units per CTA
#define NC    32           // gate columns per CTA (4 gates x NU)
#define NTHR  512          // 16 warps = 8 k-groups x 2 batch-halves
#define NGRP  8
#define XKG   (DIN_/NGRP)  // 32 x-k per group
#define HKG   (H_/NGRP)    // 128 h-k per group

// SMEM layout (floats)
#define SM_WX (DIN_*NC)        // 8192
#define SM_WH (H_*NC)          // 32768
#define SM_Z  (NGRP*16*B_*2)   // 16384  (per-group partial z, 64-bit cells)
#define SM_C  (B_*NU)          // 512
#define SM_B  (NC)             // 32
#define SMEM_FLOATS (SM_WX+SM_WH+SM_Z+SM_C+SM_B)
#define SMEM_BYTES  (SMEM_FLOATS*4)   // 231,552 B

// ---------------- device scratch (static; no runtime allocation) ----------------
__device__ float g_hs[(size_t)T_*H_*B_];          // [t][h][b]  transposed (128 MB)
__device__ float g_xT[(size_t)T_*DIN_*B_];        // [t][d][b]  transposed x
__device__ float g_xz[(size_t)NCTA*T_*NC*B_];     // [cta][t][col][b] = x@Wx + b (512 MB)
__device__ int   g_cnt[T_];                       // monotonic per-step counters
__device__ int   g_xflag[NCTA];                   // transpose-done flags (monotonic)

// ---------------- f32x2 helpers ----------------
static __device__ __forceinline__ unsigned long long pack2(float lo, float hi) {
    unsigned long long r;
    asm("mov.b64 %0, {%1, %2};" : "=l"(r) : "f"(lo), "f"(hi));
    return r;
}
static __device__ __forceinline__ unsigned long long fma2(unsigned long long a,
                                                          unsigned long long b,
                                                          unsigned long long c) {
    unsigned long long d;
    asm("fma.rn.f32x2 %0, %1, %2, %3;" : "=l"(d) : "l"(a), "l"(b), "l"(c));
    return d;
}
static __device__ __forceinline__ void unpack2(unsigned long long v, float &lo, float &hi) {
    asm("mov.b64 {%0, %1}, %2;" : "=f"(lo), "=f"(hi) : "l"(v));
}
static __device__ __forceinline__ int ld_acq(const int* p) {
    int v;
    asm volatile("ld.acquire.gpu.s32 %0, [%1];" : "=r"(v) : "l"(p) : "memory");
    return v;
}
static __device__ __forceinline__ void st_rel(int* p, int v) {
    asm volatile("st.release.gpu.s32 [%0], %1;" :: "l"(p), "r"(v) : "memory");
}
static __device__ __forceinline__ void red_rel_add(int* p, int v) {
    asm volatile("red.release.gpu.global.add.s32 [%0], %1;" :: "l"(p), "r"(v) : "memory");
}

// One k of the recurrence GEMM. wrow: SMEM weight row (+colbase), 8 cols as
// 4 pre-packed f32x2 col-pairs; arow: GLOBAL activation row (+batbase), 4 bats.
// acc[cp][b]: col-pair cp (2 cols), bat b.  16 FFMA2 per call. LDG issued first.
static __device__ __forceinline__ void kstep(const float* __restrict__ wrow,
                                             const float* __restrict__ arow,
                                             unsigned long long acc[4][4]) {
    float4 a = __ldcg((const float4*)(arow));         // 4 bats from L2 (longest latency)
    ulonglong2 wA = *(const ulonglong2*)(wrow);       // col-pairs 0,1
    ulonglong2 wB = *(const ulonglong2*)(wrow + 4);   // col-pairs 2,3
    unsigned long long ab[4] = {pack2(a.x, a.x), pack2(a.y, a.y),
                                pack2(a.z, a.z), pack2(a.w, a.w)};
    #pragma unroll
    for (int b = 0; b < 4; ++b) {
        acc[0][b] = fma2(wA.x, ab[b], acc[0][b]);
        acc[1][b] = fma2(wA.y, ab[b], acc[1][b]);
        acc[2][b] = fma2(wB.x, ab[b], acc[2][b]);
        acc[3][b] = fma2(wB.y, ab[b], acc[3][b]);
    }
}

// ==================== megakernel: transpose -> xz prepass -> scan -> projection ====================
__global__ void __launch_bounds__(NTHR, 1)
mega_kernel(const float* __restrict__ x, const float* __restrict__ Wx,
            const float* __restrict__ Wh, const float* __restrict__ bias,
            const float* __restrict__ Wo, const float* __restrict__ bo,
            float* __restrict__ out) {
    extern __shared__ float sm[];
    float* Wx_s = sm;                 // [DIN_][NC]
    float* Wh_s = Wx_s + SM_WX;       // [H_][NC]
    float* z_sh = Wh_s + SM_WH;       // [grp][cpg(16)][B_][2]
    float* c_sh = z_sh + SM_Z;        // [u*64 + b]
    float* b_sh = c_sh + SM_C;        // [NC]

    const int tid  = threadIdx.x;
    const int cta  = blockIdx.x;
    const int u0   = cta * NU;

    // epoch base: read BEFORE any CTA can increment this launch.
    const int base = ld_acq(&g_cnt[0]);
    const int rep1 = base / NCTA + 1;

    // ---------- phase 0: transpose x[b][t][d] -> g_xT[t][d][b] (4 t's per CTA) ----------
    {
        const int t0x = cta * 4;
        for (int tt = 0; tt < 4; ++tt) {
            const int t = t0x + tt;
            for (int id = tid; id < 1024; id += NTHR) {
                int dq = id >> 4, bq = id & 15;
                const float* xs = x + (size_t)(bq * 4) * (T_ * DIN_) + (size_t)t * DIN_ + dq * 4;
                float4 r0 = __ldcs((const float4*)(xs));
                float4 r1 = __ldcs((const float4*)(xs + T_ * DIN_));
                float4 r2 = __ldcs((const float4*)(xs + 2 * T_ * DIN_));
                float4 r3 = __ldcs((const float4*)(xs + 3 * T_ * DIN_));
                float* xd = g_xT + (size_t)t * (DIN_ * B_) + (size_t)(dq * 4) * B_ + bq * 4;
                *(float4*)(xd)          = make_float4(r0.x, r1.x, r2.x, r3.x);
                *(float4*)(xd + B_)     = make_float4(r0.y, r1.y, r2.y, r3.y);
                *(float4*)(xd + 2 * B_) = make_float4(r0.z, r1.z, r2.z, r3.z);
                *(float4*)(xd + 3 * B_) = make_float4(r0.w, r1.w, r2.w, r3.w);
            }
        }
        __threadfence();
        __syncthreads();
        if (tid == 0) st_rel(&g_xflag[cta], rep1);
    }

    // ---------- one-time weight gather into SMEM ----------
    for (int idx = tid; idx < SM_WX; idx += NTHR) {
        int k = idx >> 5, lc = idx & 31;
        int gate = lc >> 3, unit = lc & 7;
        Wx_s[idx] = Wx[(size_t)k * G4_ + gate * H_ + u0 + unit];
    }
    for (int idx = tid; idx < SM_WH; idx += NTHR) {
        int k = idx >> 5, lc = idx & 31;
        int gate = lc >> 3, unit = lc & 7;
        Wh_s[idx] = Wh[(size_t)k * G4_ + gate * H_ + u0 + unit];
    }
    if (tid < NC) {
        int gate = tid >> 3, unit = tid & 7;
        b_sh[tid] = bias[gate * H_ + u0 + unit];
    }
    for (int idx = tid; idx < SM_C; idx += NTHR) c_sh[idx] = 0.f;

    // wait for ALL transposes
    if (tid < NCTA) {
        while (ld_acq(&g_xflag[tid]) < rep1) { __nanosleep(64); }
    }
    __syncthreads();

    // ---------- role mappings ----------
    const int w    = tid >> 5;            // warp 0..15
    const int grp  = w >> 1;              // k-group 0..7
    const int half = w & 1;               // batch half
    const int lane = tid & 31;
    const int cq   = lane >> 3;           // col-pairs cq*4..+3 (cols cq*8..+7)
    const int colbase = cq * 8;
    const int batbase = half * 32 + (lane & 7) * 4;   // 4 bats per thread
    const int xk0 = grp * XKG;
    const int hk0 = grp * HKG;
    const float* wpx = Wx_s + xk0 * NC + colbase;
    const float* wph = Wh_s + hk0 * NC + colbase;

    // cell/xz mapping: 1 cell per thread
    const int cu = tid >> 6;              // unit 0..7
    const int cb = tid & 63;              // batch 0..63

    float* xz_cta = g_xz + (size_t)cta * (T_ * NC * B_);

    // ---------- phase 1: xz prepass — xz[t] = x_t @ Wx + b, all t, no inter-CTA sync ----------
    for (int t = 0; t < T_; ++t) {
        unsigned long long acc[4][4];
        #pragma unroll
        for (int cp = 0; cp < 4; ++cp)
            #pragma unroll
            for (int b = 0; b < 4; ++b) acc[cp][b] = 0ull;

        const float* ap = g_xT + (size_t)t * (DIN_ * B_) + xk0 * B_ + batbase;
        #pragma unroll 8
        for (int kk = 0; kk < XKG; ++kk)
            kstep(wpx + kk * NC, ap + kk * B_, acc);

        #pragma unroll
        for (int cp = 0; cp < 4; ++cp)
            #pragma unroll
            for (int b = 0; b < 4; ++b)
                *(unsigned long long*)(z_sh + (size_t)((grp * 16 + cq * 4 + cp) * B_
                                                       + batbase + b) * 2) = acc[cp][b];
        __syncthreads();

        float* xzrow = xz_cta + (size_t)t * (NC * B_);
        #pragma unroll
        for (int g = 0; g < 4; ++g) {
            int col = g * 8 + cu;
            int cpg = col >> 1, par = col & 1;
            float s = b_sh[col];
            #pragma unroll
            for (int gg2 = 0; gg2 < NGRP; ++gg2)
                s += z_sh[((gg2 * 16 + cpg) * B_ + cb) * 2 + par];
            xzrow[col * B_ + cb] = s;
        }
        __syncthreads();
    }

    // ---------- phase 2: scan (h-only inner loop) ----------
    for (int t = 0; t < T_; ++t) {
        // prefetch this CTA's xz[t] for the cell update (independent of h flag)
        const float* xzrow = xz_cta + (size_t)t * (NC * B_);
        float xzv[4];
        #pragma unroll
        for (int g = 0; g < 4; ++g)
            xzv[g] = __ldcg(xzrow + (g * 8 + cu) * B_ + cb);

        unsigned long long acc[4][4];
        #pragma unroll
        for (int cp = 0; cp < 4; ++cp)
            #pragma unroll
            for (int b = 0; b < 4; ++b) acc[cp][b] = 0ull;

        if (t > 0) {
            if (lane == 0) {
                while (ld_acq(&g_cnt[t - 1]) < base + NCTA) { __nanosleep(32); }
            }
            __syncwarp();
            const float* ap = g_hs + (size_t)(t - 1) * (H_ * B_) + hk0 * B_ + batbase;
            #pragma unroll 8
            for (int kk = 0; kk < HKG; ++kk)
                kstep(wph + kk * NC, ap + kk * B_, acc);
        }

        // publish partial z (64-bit cells: [grp][cpg][bat][2])
        #pragma unroll
        for (int cp = 0; cp < 4; ++cp)
            #pragma unroll
            for (int b = 0; b < 4; ++b)
                *(unsigned long long*)(z_sh + (size_t)((grp * 16 + cq * 4 + cp) * B_
                                                       + batbase + b) * 2) = acc[cp][b];
        __syncthreads();

        // cell update: 512 cells, 1 per thread (bias already folded into xz)
        {
            float zg[4];
            #pragma unroll
            for (int g = 0; g < 4; ++g) {
                int col = g * 8 + cu;
                int cpg = col >> 1, par = col & 1;
                float s = xzv[g];
                #pragma unroll
                for (int gg2 = 0; gg2 < NGRP; ++gg2)
                    s += z_sh[((gg2 * 16 + cpg) * B_ + cb) * 2 + par];
                zg[g] = s;
            }
            float ig = 1.f / (1.f + expf(-zg[0]));
            float fg = 1.f / (1.f + expf(-zg[1]));
            float gv = tanhf(zg[2]);
            float og = 1.f / (1.f + expf(-zg[3]));
            float cv = fg * c_sh[cu * B_ + cb] + ig * gv;
            c_sh[cu * B_ + cb] = cv;
            g_hs[(size_t)t * (H_ * B_) + (size_t)(u0 + cu) * B_ + cb] = og * tanhf(cv);
        }

        // release h_t: bar.sync orders intra-CTA; elected release publishes at gpu scope
        __syncthreads();
        if (tid == 0) red_rel_add(&g_cnt[t], 1);
    }

    // ---------- phase 3: projection relu(hs @ Wo + bo); CTA i does t = 4i..4i+3 ----------
    const int t0p = cta * 4;
    if (tid < 4) {
        while (ld_acq(&g_cnt[t0p + tid]) < base + NCTA) { __nanosleep(64); }
    }
    __syncthreads();

    float* h_sh  = sm;            // [32][B_]    = 2048 floats (overlay)
    float* Wo_sh = sm + 2048;     // [32][DOUT_] = 8192 floats

    const int bb = tid >> 3;            // batch 0..63
    const int nq = (tid & 7) * 4;       // col sub-offset; covers nq + 32*j, j=0..7

    for (int tt = 0; tt < 4; ++tt) {
        const int t = t0p + tt;
        unsigned long long acc2[8][2];
        #pragma unroll
        for (int j = 0; j < 8; ++j) { acc2[j][0] = 0ull; acc2[j][1] = 0ull; }

        for (int k0 = 0; k0 < H_; k0 += 32) {
            const float* hsrc = g_hs + (size_t)t * (H_ * B_) + (size_t)k0 * B_;
            *(float4*)(h_sh + tid * 4) = __ldcg((const float4*)(hsrc + tid * 4));
            const float* wsrc = Wo + (size_t)k0 * DOUT_;
            #pragma unroll
            for (int q = 0; q < 4; ++q)
                *(float4*)(Wo_sh + tid * 16 + q * 4) =
                    __ldcg((const float4*)(wsrc + tid * 16 + q * 4));
            __syncthreads();

            #pragma unroll 8
            for (int kk = 0; kk < 32; ++kk) {
                float av = h_sh[kk * B_ + bb];
                unsigned long long aa = pack2(av, av);
                const float* wr = Wo_sh + kk * DOUT_ + nq;
                #pragma unroll
                for (int j = 0; j < 8; ++j) {
                    ulonglong2 w2 = *(const ulonglong2*)(wr + 32 * j);
                    acc2[j][0] = fma2(w2.x, aa, acc2[j][0]);
                    acc2[j][1] = fma2(w2.y, aa, acc2[j][1]);
                }
            }
            __syncthreads();
        }

        float* orow = out + (size_t)bb * (T_ * DOUT_) + (size_t)t * DOUT_;
        #pragma unroll
        for (int j = 0; j < 8; ++j) {
            int n = nq + 32 * j;
            float o0, o1, o2, o3;
            unpack2(acc2[j][0], o0, o1);
            unpack2(acc2[j][1], o2, o3);
            float4 r;
            r.x = fmaxf(o0 + bo[n + 0], 0.f);
            r.y = fmaxf(o1 + bo[n + 1], 0.f);
            r.z = fmaxf(o2 + bo[n + 2], 0.f);
            r.w = fmaxf(o3 + bo[n + 3], 0.f);
            *(float4*)(orow + n) = r;
        }
    }
}

extern "C" void kernel_launch(void* const* d_in, const int* in_sizes, int n_in,
                              void* d_out, int out_size) {
    const float* x  = (const float*)d_in[0];
    const float* Wx = (const float*)d_in[1];
    const float* Wh = (const float*)d_in[2];
    const float* b  = (const float*)d_in[3];
    const float* Wo = (const float*)d_in[4];
    const float* bo = (const float*)d_in[5];
    float* out = (float*)d_out;

    cudaFuncSetAttribute(mega_kernel, cudaFuncAttributeMaxDynamicSharedMemorySize,
                         SMEM_BYTES);
    mega_kernel<<<NCTA, NTHR, SMEM_BYTES>>>(x, Wx, Wh, b, Wo, bo, out);
}